// round 9
// baseline (speedup 1.0000x reference)
#include <cuda_runtime.h>
#include <math_constants.h>
#include <float.h>

// Problem constants (fixed by setup_inputs): B=64, Nt=64, Ns=4096, C=256,
// WIN=2, TOPK=3, GH=GW=4, 16 gabor kernels.
#define BMAX 64

// Per (batch, block-row-pair) top-3 candidates: 16 blocks x 3 per batch.
__device__ float g_cand_v[BMAX * 48];
__device__ int   g_cand_i[BMAX * 48];
__device__ float g_gmap[16];

__device__ __forceinline__ float4 max4(float4 a, float4 b) {
    return make_float4(fmaxf(a.x, b.x), fmaxf(a.y, b.y),
                       fmaxf(a.z, b.z), fmaxf(a.w, b.w));
}

// better(v,i, w,j): strictly greater value, or equal value with lower index
// (matches jax.lax.top_k ordering).
__device__ __forceinline__ bool better(float v, int i, float w, int j) {
    return v > w || (v == w && i < j);
}
__device__ __forceinline__ void insert3(float v, int i, float* rv, int* ri) {
    if (better(v, i, rv[0], ri[0])) {
        rv[2] = rv[1]; ri[2] = ri[1];
        rv[1] = rv[0]; ri[1] = ri[0];
        rv[0] = v;     ri[0] = i;
    } else if (better(v, i, rv[1], ri[1])) {
        rv[2] = rv[1]; ri[2] = ri[1];
        rv[1] = v;     ri[1] = i;
    } else if (better(v, i, rv[2], ri[2])) {
        rv[2] = v;     ri[2] = i;
    }
}

// ---------------------------------------------------------------------------
// Main kernel. grid = B*16 + 1.
// Block B*16: 4x4 gabor map, fully parallel (16 cells x 16 kernels).
// Blocks [0, B*16): b = blk>>4, whp = blk&15 -> window rows 2*whp, 2*whp+1.
//   1. zmax[b] preamble (redundant 16x per batch -> 64MB L2 traffic, half of
//      the previous scheme; overlaps the latency-bound start of the x read).
//   2. 64 window sums: 8 warps x (2 rows x 4 windows); streaming float4
//      loads front-batched per pixel-row; shuffle-reduce.
//   3. Block-local top-3 of its 64 windows (any global top-3 member is in
//      some block's local top-3) -> 3 (value,index) candidates to gmem.
// ---------------------------------------------------------------------------
__global__ void __launch_bounds__(256) k_main(
        const float* __restrict__ x, const float* __restrict__ z, int B,
        const float* __restrict__ gth, const float* __restrict__ gsg,
        const float* __restrict__ glm, const float* __restrict__ gps,
        const float* __restrict__ ggm, const float* __restrict__ gwt) {
    int blk = blockIdx.x;
    int tid = threadIdx.x;

    if (blk == B * 16) {   // gabor block
        int cell = tid >> 4;       // 0..15 -> (h,w)
        int k    = tid & 15;       // gabor kernel index
        int h = cell >> 2, w = cell & 3;
        float yy = (float)h - 1.5f;
        float xx = (float)w - 1.5f;
        float theta = gth[k] * (2.f * CUDART_PI_F);
        float ct = cosf(theta), st = sinf(theta);
        float xp =  xx * ct + yy * st;
        float yp = -xx * st + yy * ct;
        float sig = gsg[k] + 0.5f;
        float lmb = glm[k] + 0.5f;
        float gam = ggm[k];
        float env = expf(-(xp * xp + gam * gam * yp * yp) / (2.f * sig * sig));
        float car = cosf(2.f * CUDART_PI_F * xp / lmb + gps[k]);
        float term = gwt[k] * env * car;
#pragma unroll
        for (int o = 8; o > 0; o >>= 1)
            term += __shfl_down_sync(0xffffffffu, term, o, 16);
        if (k == 0) g_gmap[cell] = 1.f + term;  // splat + x_up = x_up*(1+gmap)
        return;
    }

    int b   = blk >> 4;
    int whp = blk & 15;            // window-row pair: rows 2*whp, 2*whp+1
    __shared__ float4 szg[4][64];
    __shared__ float4 sz[64];

    // --- 1. zmax[b] preamble ---
    {
        int g  = tid >> 6;       // token group 0..3 (16 tokens each)
        int c4 = tid & 63;       // float4 channel lane
        const float4* zp = (const float4*)(z + ((size_t)b * 64 + g * 16) * 256) + c4;
        float4 m = __ldg(zp);
#pragma unroll
        for (int t = 1; t < 16; ++t) m = max4(m, __ldg(zp + t * 64));
        szg[g][c4] = m;
    }
    __syncthreads();
    if (tid < 64)
        sz[tid] = max4(max4(szg[0][tid], szg[1][tid]),
                       max4(szg[2][tid], szg[3][tid]));
    __syncthreads();

    // --- 2. window sums for 2 rows ---
    int warp = tid >> 5, lane = tid & 31;
    float4 za = sz[lane], zb = sz[lane + 32];
    float acc[2][4];
#pragma unroll
    for (int wl = 0; wl < 2; ++wl)
#pragma unroll
        for (int q = 0; q < 4; ++q) acc[wl][q] = 0.f;

#pragma unroll
    for (int wl = 0; wl < 2; ++wl) {
        int wh = whp * 2 + wl;
        const float* xb = x + (size_t)b * 4096 * 256 + (size_t)wh * 128 * 256
                            + (size_t)warp * 4 * 2 * 256;
#pragma unroll
        for (int r = 0; r < 4; ++r) {
            int off = ((r >> 1) * 64 + (r & 1)) * 256;  // rows s, s+1, s+64, s+65
            float4 va[4], vb[4];
#pragma unroll
            for (int q = 0; q < 4; ++q) {               // batch 8 loads
                const float4* p4 = (const float4*)(xb + q * 512 + off);
                va[q] = __ldcs(p4 + lane);
                vb[q] = __ldcs(p4 + lane + 32);
            }
#pragma unroll
            for (int q = 0; q < 4; ++q) {
                acc[wl][q] += va[q].x * za.x + va[q].y * za.y
                            + va[q].z * za.z + va[q].w * za.w;
                acc[wl][q] += vb[q].x * zb.x + vb[q].y * zb.y
                            + vb[q].z * zb.z + vb[q].w * zb.w;
            }
        }
    }

    // --- 3. block-local top-3 -> candidates ---
    __shared__ float wv[8][3];
    __shared__ int   wi[8][3];
    float rv[3] = {-FLT_MAX, -FLT_MAX, -FLT_MAX};
    int   ri[3] = {1 << 30, 1 << 30, 1 << 30};

#pragma unroll
    for (int wl = 0; wl < 2; ++wl)
#pragma unroll
        for (int q = 0; q < 4; ++q) {
            float a = acc[wl][q];
#pragma unroll
            for (int o = 16; o > 0; o >>= 1)
                a += __shfl_down_sync(0xffffffffu, a, o);
            if (lane == 0) {
                int i = (whp * 2 + wl) * 32 + warp * 4 + q;  // global window id
                insert3(a, i, rv, ri);
            }
        }
    if (lane == 0) {
#pragma unroll
        for (int s = 0; s < 3; ++s) { wv[warp][s] = rv[s]; wi[warp][s] = ri[s]; }
    }
    __syncthreads();
    if (warp == 0) {
        float fv[3] = {-FLT_MAX, -FLT_MAX, -FLT_MAX};
        int   fi[3] = {1 << 30, 1 << 30, 1 << 30};
        if (lane < 8) {
#pragma unroll
            for (int s = 0; s < 3; ++s) { fv[s] = wv[lane][s]; fi[s] = wi[lane][s]; }
        }
#pragma unroll
        for (int o = 4; o > 0; o >>= 1) {
            float ov[3]; int oi[3];
#pragma unroll
            for (int s = 0; s < 3; ++s) {
                ov[s] = __shfl_down_sync(0xffffffffu, fv[s], o);
                oi[s] = __shfl_down_sync(0xffffffffu, fi[s], o);
            }
#pragma unroll
            for (int s = 0; s < 3; ++s) insert3(ov[s], oi[s], fv, fi);
        }
        if (lane == 0) {
#pragma unroll
            for (int s = 0; s < 3; ++s) {
                g_cand_v[(b * 16 + whp) * 3 + s] = fv[s];
                g_cand_i[(b * 16 + whp) * 3 + s] = fi[s];
            }
        }
    }
}

// ---------------------------------------------------------------------------
// Tail: grid = B*3, 256 threads. Block (b, t): warp 0 merges the batch's 48
// candidates (lane l takes cand l and l+32 if <48; 5 shuffle steps), then all
// threads handle window rank t: gather 2x2 corners, bilinear 2->4 upsample,
// (1+gmap) scale, write 16 cells x 256 channels.
// jax half-pixel bilinear 2->4 weights: {1,0},{.75,.25},{.25,.75},{0,1}.
// ---------------------------------------------------------------------------
__global__ void __launch_bounds__(256) k_tail(const float* __restrict__ x,
                                              float* __restrict__ out) {
    int b = blockIdx.x / 3;
    int t = blockIdx.x % 3;
    __shared__ int   sidx[3];
    __shared__ float s_gmap[16];
    int tid = threadIdx.x;
    int warp = tid >> 5, lane = tid & 31;

    if (tid < 16) s_gmap[tid] = g_gmap[tid];

    if (warp == 0) {
        float rv[3] = {-FLT_MAX, -FLT_MAX, -FLT_MAX};
        int   ri[3] = {1 << 30, 1 << 30, 1 << 30};
        insert3(__ldg(&g_cand_v[b * 48 + lane]),
                __ldg(&g_cand_i[b * 48 + lane]), rv, ri);
        if (lane < 16)
            insert3(__ldg(&g_cand_v[b * 48 + 32 + lane]),
                    __ldg(&g_cand_i[b * 48 + 32 + lane]), rv, ri);
#pragma unroll
        for (int o = 16; o > 0; o >>= 1) {
            float ov[3]; int oi[3];
#pragma unroll
            for (int s = 0; s < 3; ++s) {
                ov[s] = __shfl_down_sync(0xffffffffu, rv[s], o);
                oi[s] = __shfl_down_sync(0xffffffffu, ri[s], o);
            }
#pragma unroll
            for (int s = 0; s < 3; ++s) insert3(ov[s], oi[s], rv, ri);
        }
        if (lane == 0) {
#pragma unroll
            for (int s = 0; s < 3; ++s) sidx[s] = ri[s];
        }
    }
    __syncthreads();

    const float wa[4] = {1.f, 0.75f, 0.25f, 0.f};
    const float wb[4] = {0.f, 0.25f, 0.75f, 1.f};
    int c = tid;

    int widx = sidx[t];
    int wh = widx >> 5, ww = widx & 31;
    const float* p = x + ((size_t)b * 4096 + wh * 128 + ww * 2) * 256 + c;
    float v00 = p[0];          // (i=0,j=0)
    float v01 = p[256];        // (i=0,j=1)
    float v10 = p[64 * 256];   // (i=1,j=0)
    float v11 = p[65 * 256];   // (i=1,j=1)

    float* ob = out + ((size_t)b * 48 + t * 16) * 256 + c;
#pragma unroll
    for (int gh = 0; gh < 4; ++gh) {
        float u0 = wa[gh] * v00 + wb[gh] * v10;  // interp along i (rows)
        float u1 = wa[gh] * v01 + wb[gh] * v11;
#pragma unroll
        for (int gw = 0; gw < 4; ++gw) {
            float val = wa[gw] * u0 + wb[gw] * u1;  // interp along j (cols)
            ob[(gh * 4 + gw) * 256] = val * s_gmap[gh * 4 + gw];
        }
    }
}

// ---------------------------------------------------------------------------
extern "C" void kernel_launch(void* const* d_in, const int* in_sizes, int n_in,
                              void* d_out, int out_size) {
    const float* z   = (const float*)d_in[0];
    const float* x   = (const float*)d_in[1];
    const float* gth = (const float*)d_in[2];
    const float* gsg = (const float*)d_in[3];
    const float* glm = (const float*)d_in[4];
    const float* gps = (const float*)d_in[5];
    const float* ggm = (const float*)d_in[6];
    const float* gwt = (const float*)d_in[7];
    float* out = (float*)d_out;

    int B = in_sizes[0] / (64 * 256);   // z is (B, 64, 256)

    k_main<<<B * 16 + 1, 256>>>(x, z, B, gth, gsg, glm, gps, ggm, gwt);
    k_tail<<<B * 3,      256>>>(x, out);
}

// round 10
// speedup vs baseline: 1.0091x; 1.0091x over previous
#include <cuda_runtime.h>
#include <math_constants.h>
#include <float.h>

// Problem constants (fixed by setup_inputs): B=64, Nt=64, Ns=4096, C=256,
// WIN=2, TOPK=3, GH=GW=4, 16 gabor kernels.
#define BMAX 64

// Per-block top-3 candidates: 32 blocks x 3 per batch.
__device__ float g_cand_v[BMAX * 96];
__device__ int   g_cand_i[BMAX * 96];
__device__ int   g_count[BMAX];          // zero-init; each launch leaves it zero

__device__ __forceinline__ float4 max4(float4 a, float4 b) {
    return make_float4(fmaxf(a.x, b.x), fmaxf(a.y, b.y),
                       fmaxf(a.z, b.z), fmaxf(a.w, b.w));
}

// better(v,i, w,j): strictly greater value, or equal value with lower index
// (matches jax.lax.top_k ordering).
__device__ __forceinline__ bool better(float v, int i, float w, int j) {
    return v > w || (v == w && i < j);
}
__device__ __forceinline__ void insert3(float v, int i, float* rv, int* ri) {
    if (better(v, i, rv[0], ri[0])) {
        rv[2] = rv[1]; ri[2] = ri[1];
        rv[1] = rv[0]; ri[1] = ri[0];
        rv[0] = v;     ri[0] = i;
    } else if (better(v, i, rv[1], ri[1])) {
        rv[2] = rv[1]; ri[2] = ri[1];
        rv[1] = v;     ri[1] = i;
    } else if (better(v, i, rv[2], ri[2])) {
        rv[2] = v;     ri[2] = i;
    }
}

// ---------------------------------------------------------------------------
// Single fused kernel. grid = B*32, 256 threads. Block (b, wh):
//   1. zmax[b] preamble (redundant across the batch's 32 blocks; z replays
//      are L2 hits overlapping the latency-bound start of the x stream).
//   2. winsum for its 32 windows: 8 warps x 4 windows, streaming float4
//      loads front-batched per pixel-row, shuffle reduce.
//   3. Block-local top-3 (from register sums) -> 3 candidates to gmem,
//      fence, atomic ticket.
//   4. LAST arriving block of batch b: fast-math gabor map, warp-0 merge of
//      the 96 candidates, batched 12-load gather of the 3 selected windows,
//      bilinear 2->4 upsample, (1+gmap) scale, write. Short chain (~2us),
//      overlapped with other batches' streaming except in the final wave.
// ---------------------------------------------------------------------------
__global__ void __launch_bounds__(256) k_main(
        const float* __restrict__ x, const float* __restrict__ z,
        float* __restrict__ out,
        const float* __restrict__ gth, const float* __restrict__ gsg,
        const float* __restrict__ glm, const float* __restrict__ gps,
        const float* __restrict__ ggm, const float* __restrict__ gwt) {
    int blk = blockIdx.x;
    int tid = threadIdx.x;
    int b  = blk >> 5;
    int wh = blk & 31;

    __shared__ float4 szg[4][64];
    __shared__ float4 sz[64];

    // --- 1. zmax[b] preamble ---
    {
        int g  = tid >> 6;       // token group 0..3 (16 tokens each)
        int c4 = tid & 63;       // float4 channel lane
        const float4* zp = (const float4*)(z + ((size_t)b * 64 + g * 16) * 256) + c4;
        float4 m = __ldg(zp);
#pragma unroll
        for (int t = 1; t < 16; ++t) m = max4(m, __ldg(zp + t * 64));
        szg[g][c4] = m;
    }
    __syncthreads();
    if (tid < 64)
        sz[tid] = max4(max4(szg[0][tid], szg[1][tid]),
                       max4(szg[2][tid], szg[3][tid]));
    __syncthreads();

    // --- 2. winsum ---
    int warp = tid >> 5, lane = tid & 31;
    const float* xb = x + (size_t)b * 4096 * 256 + (size_t)wh * 128 * 256
                        + (size_t)warp * 4 * 2 * 256;

    float acc[4] = {0.f, 0.f, 0.f, 0.f};
#pragma unroll
    for (int r = 0; r < 4; ++r) {
        int off = ((r >> 1) * 64 + (r & 1)) * 256;   // rows s, s+1, s+64, s+65
        float4 va[4], vb[4];
#pragma unroll
        for (int q = 0; q < 4; ++q) {                // batch 8 loads before FMAs
            const float4* p4 = (const float4*)(xb + q * 512 + off);
            va[q] = __ldcs(p4 + lane);
            vb[q] = __ldcs(p4 + lane + 32);
        }
        float4 za = sz[lane], zb = sz[lane + 32];
#pragma unroll
        for (int q = 0; q < 4; ++q) {
            acc[q] += va[q].x * za.x + va[q].y * za.y + va[q].z * za.z + va[q].w * za.w;
            acc[q] += vb[q].x * zb.x + vb[q].y * zb.y + vb[q].z * zb.z + vb[q].w * zb.w;
        }
    }

    // --- 3. block-local top-3 -> candidates, ticket ---
    __shared__ float wv[8][3];
    __shared__ int   wi[8][3];
    {
        float rv[3] = {-FLT_MAX, -FLT_MAX, -FLT_MAX};
        int   ri[3] = {1 << 30, 1 << 30, 1 << 30};
#pragma unroll
        for (int q = 0; q < 4; ++q) {
            float a = acc[q];
#pragma unroll
            for (int o = 16; o > 0; o >>= 1)
                a += __shfl_down_sync(0xffffffffu, a, o);
            if (lane == 0) insert3(a, wh * 32 + warp * 4 + q, rv, ri);
        }
        if (lane == 0) {
#pragma unroll
            for (int s = 0; s < 3; ++s) { wv[warp][s] = rv[s]; wi[warp][s] = ri[s]; }
        }
    }
    __syncthreads();

    __shared__ int s_last;
    if (warp == 0) {
        float fv[3] = {-FLT_MAX, -FLT_MAX, -FLT_MAX};
        int   fi[3] = {1 << 30, 1 << 30, 1 << 30};
        if (lane < 8) {
#pragma unroll
            for (int s = 0; s < 3; ++s) { fv[s] = wv[lane][s]; fi[s] = wi[lane][s]; }
        }
#pragma unroll
        for (int o = 4; o > 0; o >>= 1) {
            float ov[3]; int oi[3];
#pragma unroll
            for (int s = 0; s < 3; ++s) {
                ov[s] = __shfl_down_sync(0xffffffffu, fv[s], o);
                oi[s] = __shfl_down_sync(0xffffffffu, fi[s], o);
            }
#pragma unroll
            for (int s = 0; s < 3; ++s) insert3(ov[s], oi[s], fv, fi);
        }
        if (lane == 0) {
#pragma unroll
            for (int s = 0; s < 3; ++s) {
                g_cand_v[(b * 32 + wh) * 3 + s] = fv[s];
                g_cand_i[(b * 32 + wh) * 3 + s] = fi[s];
            }
            __threadfence();                       // publish candidates
            int old = atomicAdd(&g_count[b], 1);
            s_last = (old == 31);
            if (old == 31) {
                g_count[b] = 0;                    // reset for next replay
                __threadfence();                   // acquire side
            }
        }
    }
    __syncthreads();
    if (!s_last) return;

    // ================= 4. epilogue (one block per batch) =================
    __shared__ int   sidx[3];
    __shared__ float s_gmap[16];

    // Gabor map: tid = cell*16 + k, fast intrinsics (tolerance 1e-3).
    {
        int cell = tid >> 4;
        int k    = tid & 15;
        int h = cell >> 2, w = cell & 3;
        float yy = (float)h - 1.5f;
        float xx = (float)w - 1.5f;
        float theta = gth[k] * (2.f * CUDART_PI_F);
        float ct = __cosf(theta), st = __sinf(theta);
        float xp =  xx * ct + yy * st;
        float yp = -xx * st + yy * ct;
        float sig = gsg[k] + 0.5f;
        float lmb = glm[k] + 0.5f;
        float gam = ggm[k];
        float env = __expf(-(xp * xp + gam * gam * yp * yp) / (2.f * sig * sig));
        float car = __cosf(2.f * CUDART_PI_F * xp / lmb + gps[k]);
        float term = gwt[k] * env * car;
#pragma unroll
        for (int o = 8; o > 0; o >>= 1)
            term += __shfl_down_sync(0xffffffffu, term, o, 16);
        if (k == 0) s_gmap[cell] = 1.f + term;  // splat + x_up = x_up*(1+gmap)
    }

    // Warp 0: merge the batch's 96 candidates (3 per lane, 5 shuffle rounds).
    if (warp == 0) {
        float rv[3] = {-FLT_MAX, -FLT_MAX, -FLT_MAX};
        int   ri[3] = {1 << 30, 1 << 30, 1 << 30};
#pragma unroll
        for (int s = 0; s < 3; ++s)
            insert3(__ldcg(&g_cand_v[b * 96 + lane * 3 + s]),
                    __ldcg(&g_cand_i[b * 96 + lane * 3 + s]), rv, ri);
#pragma unroll
        for (int o = 16; o > 0; o >>= 1) {
            float ov[3]; int oi[3];
#pragma unroll
            for (int s = 0; s < 3; ++s) {
                ov[s] = __shfl_down_sync(0xffffffffu, rv[s], o);
                oi[s] = __shfl_down_sync(0xffffffffu, ri[s], o);
            }
#pragma unroll
            for (int s = 0; s < 3; ++s) insert3(ov[s], oi[s], rv, ri);
        }
        if (lane == 0) {
#pragma unroll
            for (int s = 0; s < 3; ++s) sidx[s] = ri[s];
        }
    }
    __syncthreads();

    // Batched gather: all 12 corner loads issued before any compute.
    int c = tid;
    const float* pp[3];
#pragma unroll
    for (int t = 0; t < 3; ++t) {
        int widx = sidx[t];
        pp[t] = x + ((size_t)b * 4096 + (widx >> 5) * 128 + (widx & 31) * 2) * 256 + c;
    }
    float v00[3], v01[3], v10[3], v11[3];
#pragma unroll
    for (int t = 0; t < 3; ++t) {
        v00[t] = pp[t][0];
        v01[t] = pp[t][256];
        v10[t] = pp[t][64 * 256];
        v11[t] = pp[t][65 * 256];
    }

    // jax half-pixel bilinear 2->4 weights: {1,0},{.75,.25},{.25,.75},{0,1}.
    const float wa[4] = {1.f, 0.75f, 0.25f, 0.f};
    const float wb[4] = {0.f, 0.25f, 0.75f, 1.f};
#pragma unroll
    for (int t = 0; t < 3; ++t) {
        float* ob = out + ((size_t)b * 48 + t * 16) * 256 + c;
#pragma unroll
        for (int gh = 0; gh < 4; ++gh) {
            float u0 = wa[gh] * v00[t] + wb[gh] * v10[t];  // interp along rows
            float u1 = wa[gh] * v01[t] + wb[gh] * v11[t];
#pragma unroll
            for (int gw = 0; gw < 4; ++gw) {
                float val = wa[gw] * u0 + wb[gw] * u1;     // interp along cols
                ob[(gh * 4 + gw) * 256] = val * s_gmap[gh * 4 + gw];
            }
        }
    }
}

// ---------------------------------------------------------------------------
extern "C" void kernel_launch(void* const* d_in, const int* in_sizes, int n_in,
                              void* d_out, int out_size) {
    const float* z   = (const float*)d_in[0];
    const float* x   = (const float*)d_in[1];
    const float* gth = (const float*)d_in[2];
    const float* gsg = (const float*)d_in[3];
    const float* glm = (const float*)d_in[4];
    const float* gps = (const float*)d_in[5];
    const float* ggm = (const float*)d_in[6];
    const float* gwt = (const float*)d_in[7];
    float* out = (float*)d_out;

    int B = in_sizes[0] / (64 * 256);   // z is (B, 64, 256)

    k_main<<<B * 32, 256>>>(x, z, out, gth, gsg, glm, gps, ggm, gwt);
}

// round 11
// speedup vs baseline: 1.1211x; 1.1110x over previous
#include <cuda_runtime.h>
#include <math_constants.h>
#include <float.h>

// Problem constants (fixed by setup_inputs): B=64, Nt=64, Ns=4096, C=256,
// WIN=2, TOPK=3, GH=GW=4, 16 gabor kernels.
#define BMAX 64

__device__ float g_zmax[BMAX * 256];
__device__ float g_winsum[BMAX * 1024];
__device__ float g_gmap[16];

__device__ __forceinline__ float4 max4(float4 a, float4 b) {
    return make_float4(fmaxf(a.x, b.x), fmaxf(a.y, b.y),
                       fmaxf(a.z, b.z), fmaxf(a.w, b.w));
}

// better(v,i, w,j): strictly greater value, or equal value with lower index
// (matches jax.lax.top_k ordering).
__device__ __forceinline__ bool better(float v, int i, float w, int j) {
    return v > w || (v == w && i < j);
}
__device__ __forceinline__ void insert3(float v, int i, float* rv, int* ri) {
    if (better(v, i, rv[0], ri[0])) {
        rv[2] = rv[1]; ri[2] = ri[1];
        rv[1] = rv[0]; ri[1] = ri[0];
        rv[0] = v;     ri[0] = i;
    } else if (better(v, i, rv[1], ri[1])) {
        rv[2] = rv[1]; ri[2] = ri[1];
        rv[1] = v;     ri[1] = i;
    } else if (better(v, i, rv[2], ri[2])) {
        rv[2] = v;     ri[2] = i;
    }
}

// ---------------------------------------------------------------------------
// Kernel 1: z_max (R5 geometry: measured 5.86us). grid = B*4 + 1.
// Blocks [0, B*4): b = blk/4, cg = blk%4 (64 channels). 256 threads =
// 16 token-groups x 16 float4 lanes, 4 loads each.
// Block B*4 computes the 4x4 gabor map fully in parallel (cell x k).
// ---------------------------------------------------------------------------
__global__ void __launch_bounds__(256) k_zmax(
        const float* __restrict__ z, int B,
        const float* __restrict__ gth, const float* __restrict__ gsg,
        const float* __restrict__ glm, const float* __restrict__ gps,
        const float* __restrict__ ggm, const float* __restrict__ gwt) {
    int blk = blockIdx.x;
    int tid = threadIdx.x;

    if (blk == B * 4) {   // gabor block
        int cell = tid >> 4;       // 0..15 -> (h,w)
        int k    = tid & 15;       // gabor kernel index
        int h = cell >> 2, w = cell & 3;
        float yy = (float)h - 1.5f;
        float xx = (float)w - 1.5f;
        float theta = gth[k] * (2.f * CUDART_PI_F);
        float ct = cosf(theta), st = sinf(theta);
        float xp =  xx * ct + yy * st;
        float yp = -xx * st + yy * ct;
        float sig = gsg[k] + 0.5f;
        float lmb = glm[k] + 0.5f;
        float gam = ggm[k];
        float env = expf(-(xp * xp + gam * gam * yp * yp) / (2.f * sig * sig));
        float car = cosf(2.f * CUDART_PI_F * xp / lmb + gps[k]);
        float term = gwt[k] * env * car;
#pragma unroll
        for (int o = 8; o > 0; o >>= 1)
            term += __shfl_down_sync(0xffffffffu, term, o, 16);
        if (k == 0) g_gmap[cell] = 1.f + term;  // splat + x_up = x_up*(1+gmap)
        return;
    }

    int b  = blk >> 2;
    int cg = blk & 3;              // 64-channel group
    int tg = tid >> 4;             // token group (4 tokens each)
    int c4 = tid & 15;             // float4 lane within group
    __shared__ float4 sm[16][16];

    const float4* zp = (const float4*)(z + ((size_t)b * 64 + tg * 4) * 256) + cg * 16 + c4;
    float4 m = zp[0];
    m = max4(m, zp[64]);
    m = max4(m, zp[128]);
    m = max4(m, zp[192]);
    sm[tg][c4] = m;
    __syncthreads();

    if (tid < 16) {
        float4 r = sm[0][tid];
#pragma unroll
        for (int g = 1; g < 16; ++g) r = max4(r, sm[g][tid]);
        ((float4*)(g_zmax + b * 256 + cg * 64))[tid] = r;
    }
}

// ---------------------------------------------------------------------------
// Kernel 2: winsum, 2 window-rows per block. grid = B*16, 256 threads.
// Block (b, whp) handles window rows 2*whp and 2*whp+1.
// Each warp owns 8 windows (2 rows x 4); per pixel-row-quad iteration it
// front-batches 16 float4 streaming loads (both window rows) before the FMA
// block -> 16 outstanding loads per thread for max MLP.
// winsum[b, wh*32+ww] = sum_{i,j} dot(x[b,(2wh+i)*64+2ww+j,:], zmax[b,:])
// ---------------------------------------------------------------------------
__global__ void __launch_bounds__(256) k_winsum(const float* __restrict__ x) {
    int b   = blockIdx.x >> 4;
    int whp = blockIdx.x & 15;
    __shared__ float4 sz[64];
    int tid = threadIdx.x;
    if (tid < 64) sz[tid] = ((const float4*)(g_zmax + b * 256))[tid];
    __syncthreads();

    int warp = tid >> 5, lane = tid & 31;
    float4 za = sz[lane], zb = sz[lane + 32];

    const float* x0 = x + (size_t)b * 4096 * 256
                        + (size_t)(whp * 2) * 128 * 256
                        + (size_t)warp * 4 * 2 * 256;
    const float* x1 = x0 + 128 * 256;      // second window row

    float acc[2][4];
#pragma unroll
    for (int wl = 0; wl < 2; ++wl)
#pragma unroll
        for (int q = 0; q < 4; ++q) acc[wl][q] = 0.f;

#pragma unroll
    for (int r = 0; r < 4; ++r) {
        int off = ((r >> 1) * 64 + (r & 1)) * 256;   // rows s, s+1, s+64, s+65
        float4 va[2][4], vb[2][4];
#pragma unroll
        for (int q = 0; q < 4; ++q) {                // batch 16 loads
            const float4* p0 = (const float4*)(x0 + q * 512 + off);
            const float4* p1 = (const float4*)(x1 + q * 512 + off);
            va[0][q] = __ldcs(p0 + lane);
            vb[0][q] = __ldcs(p0 + lane + 32);
            va[1][q] = __ldcs(p1 + lane);
            vb[1][q] = __ldcs(p1 + lane + 32);
        }
#pragma unroll
        for (int wl = 0; wl < 2; ++wl)
#pragma unroll
            for (int q = 0; q < 4; ++q) {
                acc[wl][q] += va[wl][q].x * za.x + va[wl][q].y * za.y
                            + va[wl][q].z * za.z + va[wl][q].w * za.w;
                acc[wl][q] += vb[wl][q].x * zb.x + vb[wl][q].y * zb.y
                            + vb[wl][q].z * zb.z + vb[wl][q].w * zb.w;
            }
    }
#pragma unroll
    for (int wl = 0; wl < 2; ++wl)
#pragma unroll
        for (int q = 0; q < 4; ++q) {
            float a = acc[wl][q];
#pragma unroll
            for (int o = 16; o > 0; o >>= 1)
                a += __shfl_down_sync(0xffffffffu, a, o);
            if (lane == 0)
                g_winsum[b * 1024 + (whp * 2 + wl) * 32 + warp * 4 + q] = a;
        }
}

// ---------------------------------------------------------------------------
// Tail (exact R8 config — best measured). grid = B*3, 256 threads.
// Block (b, t): redundant batch top-3 (warp-shuffle triple merge, 2 barriers),
// then handles window rank t: gather, bilinear 2->4, (1+gmap) scale, write.
// jax half-pixel bilinear 2->4 weights: {1,0},{.75,.25},{.25,.75},{0,1}.
// ---------------------------------------------------------------------------
__global__ void __launch_bounds__(256) k_tail(const float* __restrict__ x,
                                              float* __restrict__ out) {
    int b = blockIdx.x / 3;
    int t = blockIdx.x % 3;
    __shared__ float wv[8][3];
    __shared__ int   wi[8][3];
    __shared__ int   sidx[3];
    __shared__ float s_gmap[16];
    int tid = threadIdx.x;
    int warp = tid >> 5, lane = tid & 31;

    if (tid < 16) s_gmap[tid] = g_gmap[tid];

    float rv[3] = {-FLT_MAX, -FLT_MAX, -FLT_MAX};
    int   ri[3] = {1 << 30, 1 << 30, 1 << 30};
#pragma unroll
    for (int k = 0; k < 4; ++k) {
        int i = tid + k * 256;
        insert3(__ldg(&g_winsum[b * 1024 + i]), i, rv, ri);
    }
#pragma unroll
    for (int o = 16; o > 0; o >>= 1) {
        float ov[3]; int oi[3];
#pragma unroll
        for (int s = 0; s < 3; ++s) {
            ov[s] = __shfl_down_sync(0xffffffffu, rv[s], o);
            oi[s] = __shfl_down_sync(0xffffffffu, ri[s], o);
        }
#pragma unroll
        for (int s = 0; s < 3; ++s) insert3(ov[s], oi[s], rv, ri);
    }
    if (lane == 0) {
#pragma unroll
        for (int s = 0; s < 3; ++s) { wv[warp][s] = rv[s]; wi[warp][s] = ri[s]; }
    }
    __syncthreads();

    if (warp == 0) {
        float fv[3] = {-FLT_MAX, -FLT_MAX, -FLT_MAX};
        int   fi[3] = {1 << 30, 1 << 30, 1 << 30};
        if (lane < 8) {
#pragma unroll
            for (int s = 0; s < 3; ++s) { fv[s] = wv[lane][s]; fi[s] = wi[lane][s]; }
        }
#pragma unroll
        for (int o = 4; o > 0; o >>= 1) {
            float ov[3]; int oi[3];
#pragma unroll
            for (int s = 0; s < 3; ++s) {
                ov[s] = __shfl_down_sync(0xffffffffu, fv[s], o);
                oi[s] = __shfl_down_sync(0xffffffffu, fi[s], o);
            }
#pragma unroll
            for (int s = 0; s < 3; ++s) insert3(ov[s], oi[s], fv, fi);
        }
        if (lane == 0) {
#pragma unroll
            for (int s = 0; s < 3; ++s) sidx[s] = fi[s];
        }
    }
    __syncthreads();

    const float wa[4] = {1.f, 0.75f, 0.25f, 0.f};
    const float wb[4] = {0.f, 0.25f, 0.75f, 1.f};
    int c = tid;

    int widx = sidx[t];
    int wh = widx >> 5, ww = widx & 31;
    const float* p = x + ((size_t)b * 4096 + wh * 128 + ww * 2) * 256 + c;
    float v00 = p[0];          // (i=0,j=0)
    float v01 = p[256];        // (i=0,j=1)
    float v10 = p[64 * 256];   // (i=1,j=0)
    float v11 = p[65 * 256];   // (i=1,j=1)

    float* ob = out + ((size_t)b * 48 + t * 16) * 256 + c;
#pragma unroll
    for (int gh = 0; gh < 4; ++gh) {
        float u0 = wa[gh] * v00 + wb[gh] * v10;  // interp along i (rows)
        float u1 = wa[gh] * v01 + wb[gh] * v11;
#pragma unroll
        for (int gw = 0; gw < 4; ++gw) {
            float val = wa[gw] * u0 + wb[gw] * u1;  // interp along j (cols)
            ob[(gh * 4 + gw) * 256] = val * s_gmap[gh * 4 + gw];
        }
    }
}

// ---------------------------------------------------------------------------
extern "C" void kernel_launch(void* const* d_in, const int* in_sizes, int n_in,
                              void* d_out, int out_size) {
    const float* z   = (const float*)d_in[0];
    const float* x   = (const float*)d_in[1];
    const float* gth = (const float*)d_in[2];
    const float* gsg = (const float*)d_in[3];
    const float* glm = (const float*)d_in[4];
    const float* gps = (const float*)d_in[5];
    const float* ggm = (const float*)d_in[6];
    const float* gwt = (const float*)d_in[7];
    float* out = (float*)d_out;

    int B = in_sizes[0] / (64 * 256);   // z is (B, 64, 256)

    k_zmax  <<<B * 4 + 1, 256>>>(z, B, gth, gsg, glm, gps, ggm, gwt);
    k_winsum<<<B * 16,    256>>>(x);
    k_tail  <<<B * 3,     256>>>(x, out);
}

// round 12
// speedup vs baseline: 1.1698x; 1.0434x over previous
#include <cuda_runtime.h>
#include <math_constants.h>
#include <float.h>

// Problem constants (fixed by setup_inputs): B=64, Nt=64, Ns=4096, C=256,
// WIN=2, TOPK=3, GH=GW=4, 16 gabor kernels.
#define BMAX 64

__device__ float g_zmax[BMAX * 256];
__device__ float g_winsum[BMAX * 1024];
__device__ float g_gmap[16];
__device__ int   g_zready[BMAX];   // zero-init; 4 == batch's zmax published
__device__ int   g_wpass[BMAX];    // zero-init; counts winsum blocks past wait

__device__ __forceinline__ float4 max4(float4 a, float4 b) {
    return make_float4(fmaxf(a.x, b.x), fmaxf(a.y, b.y),
                       fmaxf(a.z, b.z), fmaxf(a.w, b.w));
}

// better(v,i, w,j): strictly greater value, or equal value with lower index
// (matches jax.lax.top_k ordering).
__device__ __forceinline__ bool better(float v, int i, float w, int j) {
    return v > w || (v == w && i < j);
}
__device__ __forceinline__ void insert3(float v, int i, float* rv, int* ri) {
    if (better(v, i, rv[0], ri[0])) {
        rv[2] = rv[1]; ri[2] = ri[1];
        rv[1] = rv[0]; ri[1] = ri[0];
        rv[0] = v;     ri[0] = i;
    } else if (better(v, i, rv[1], ri[1])) {
        rv[2] = rv[1]; ri[2] = ri[1];
        rv[1] = v;     ri[1] = i;
    } else if (better(v, i, rv[2], ri[2])) {
        rv[2] = v;     ri[2] = i;
    }
}

// ---------------------------------------------------------------------------
// Fused kernel 1. grid = B*4 + 1 + B*16, 256 threads.
//  - bids [0, B*4): zmax blocks (lowest bids -> scheduled first, wave 1).
//    b = bid/4, cg = bid%4 (64 channels). Publish slice, fence, atomic tick.
//  - bid B*4: gabor map block (fully parallel, 16 cells x 16 kernels).
//  - bids > B*4: winsum blocks, 2 window-rows each (R11 geometry).
//    Prefetch first pixel-row-quad of x (16 float4/thread in flight), THEN
//    spin on g_zready[b]==4, read zmax from L2, FMA. zmax latency hides
//    under the x-stream startup. 16th passer resets counters for replay.
// winsum[b, wh*32+ww] = sum_{i,j} dot(x[b,(2wh+i)*64+2ww+j,:], zmax[b,:])
// ---------------------------------------------------------------------------
__global__ void __launch_bounds__(256) k_main(
        const float* __restrict__ x, const float* __restrict__ z, int B,
        const float* __restrict__ gth, const float* __restrict__ gsg,
        const float* __restrict__ glm, const float* __restrict__ gps,
        const float* __restrict__ ggm, const float* __restrict__ gwt) {
    int blk = blockIdx.x;
    int tid = threadIdx.x;

    if (blk < B * 4) {   // ---------------- zmax block ----------------
        int b  = blk >> 2;
        int cg = blk & 3;              // 64-channel group
        int tg = tid >> 4;             // token group (4 tokens each)
        int c4 = tid & 15;             // float4 lane within group
        __shared__ float4 sm[16][16];

        const float4* zp = (const float4*)(z + ((size_t)b * 64 + tg * 4) * 256)
                           + cg * 16 + c4;
        float4 m = zp[0];
        m = max4(m, zp[64]);
        m = max4(m, zp[128]);
        m = max4(m, zp[192]);
        sm[tg][c4] = m;
        __syncthreads();

        if (tid < 16) {
            float4 r = sm[0][tid];
#pragma unroll
            for (int g = 1; g < 16; ++g) r = max4(r, sm[g][tid]);
            ((float4*)(g_zmax + b * 256 + cg * 64))[tid] = r;
        }
        __syncthreads();
        if (tid == 0) {
            __threadfence();                 // publish slice
            atomicAdd(&g_zready[b], 1);
        }
        return;
    }

    if (blk == B * 4) {   // ---------------- gabor block ----------------
        int cell = tid >> 4;       // 0..15 -> (h,w)
        int k    = tid & 15;       // gabor kernel index
        int h = cell >> 2, w = cell & 3;
        float yy = (float)h - 1.5f;
        float xx = (float)w - 1.5f;
        float theta = gth[k] * (2.f * CUDART_PI_F);
        float ct = cosf(theta), st = sinf(theta);
        float xp =  xx * ct + yy * st;
        float yp = -xx * st + yy * ct;
        float sig = gsg[k] + 0.5f;
        float lmb = glm[k] + 0.5f;
        float gam = ggm[k];
        float env = expf(-(xp * xp + gam * gam * yp * yp) / (2.f * sig * sig));
        float car = cosf(2.f * CUDART_PI_F * xp / lmb + gps[k]);
        float term = gwt[k] * env * car;
#pragma unroll
        for (int o = 8; o > 0; o >>= 1)
            term += __shfl_down_sync(0xffffffffu, term, o, 16);
        if (k == 0) g_gmap[cell] = 1.f + term;  // splat + x_up = x_up*(1+gmap)
        return;
    }

    // ---------------- winsum block (2 window-rows) ----------------
    int wblk = blk - (B * 4 + 1);
    int b    = wblk >> 4;
    int whp  = wblk & 15;
    int warp = tid >> 5, lane = tid & 31;

    const float* x0 = x + (size_t)b * 4096 * 256
                        + (size_t)(whp * 2) * 128 * 256
                        + (size_t)warp * 4 * 2 * 256;
    const float* x1 = x0 + 128 * 256;      // second window row

    // Prefetch pixel-row-quad r=0 (off=0): 16 float4 loads in flight.
    float4 va[2][4], vb[2][4];
#pragma unroll
    for (int q = 0; q < 4; ++q) {
        const float4* p0 = (const float4*)(x0 + q * 512);
        const float4* p1 = (const float4*)(x1 + q * 512);
        va[0][q] = __ldcs(p0 + lane);
        vb[0][q] = __ldcs(p0 + lane + 32);
        va[1][q] = __ldcs(p1 + lane);
        vb[1][q] = __ldcs(p1 + lane + 32);
    }

    // Wait for this batch's zmax (hidden under the prefetch latency).
    __shared__ float4 sz[64];
    if (tid == 0) {
        while (__ldcg(&g_zready[b]) < 4) __nanosleep(40);
        __threadfence();                   // acquire
    }
    __syncthreads();
    if (tid < 64) sz[tid] = __ldcg(((const float4*)(g_zmax + b * 256)) + tid);
    __syncthreads();
    if (tid == 0) {
        int old = atomicAdd(&g_wpass[b], 1);
        if (old == 15) { g_zready[b] = 0; g_wpass[b] = 0; }  // replay reset
    }

    float4 za = sz[lane], zb = sz[lane + 32];
    float acc[2][4];
#pragma unroll
    for (int wl = 0; wl < 2; ++wl)
#pragma unroll
        for (int q = 0; q < 4; ++q) {
            acc[wl][q]  = va[wl][q].x * za.x + va[wl][q].y * za.y
                        + va[wl][q].z * za.z + va[wl][q].w * za.w;
            acc[wl][q] += vb[wl][q].x * zb.x + vb[wl][q].y * zb.y
                        + vb[wl][q].z * zb.z + vb[wl][q].w * zb.w;
        }

#pragma unroll
    for (int r = 1; r < 4; ++r) {
        int off = ((r >> 1) * 64 + (r & 1)) * 256;   // rows s, s+1, s+64, s+65
#pragma unroll
        for (int q = 0; q < 4; ++q) {                // batch 16 loads
            const float4* p0 = (const float4*)(x0 + q * 512 + off);
            const float4* p1 = (const float4*)(x1 + q * 512 + off);
            va[0][q] = __ldcs(p0 + lane);
            vb[0][q] = __ldcs(p0 + lane + 32);
            va[1][q] = __ldcs(p1 + lane);
            vb[1][q] = __ldcs(p1 + lane + 32);
        }
#pragma unroll
        for (int wl = 0; wl < 2; ++wl)
#pragma unroll
            for (int q = 0; q < 4; ++q) {
                acc[wl][q] += va[wl][q].x * za.x + va[wl][q].y * za.y
                            + va[wl][q].z * za.z + va[wl][q].w * za.w;
                acc[wl][q] += vb[wl][q].x * zb.x + vb[wl][q].y * zb.y
                            + vb[wl][q].z * zb.z + vb[wl][q].w * zb.w;
            }
    }
#pragma unroll
    for (int wl = 0; wl < 2; ++wl)
#pragma unroll
        for (int q = 0; q < 4; ++q) {
            float a = acc[wl][q];
#pragma unroll
            for (int o = 16; o > 0; o >>= 1)
                a += __shfl_down_sync(0xffffffffu, a, o);
            if (lane == 0)
                g_winsum[b * 1024 + (whp * 2 + wl) * 32 + warp * 4 + q] = a;
        }
}

// ---------------------------------------------------------------------------
// Tail (R8 config — best measured). grid = B*3, 256 threads.
// Block (b, t): redundant batch top-3 (warp-shuffle triple merge, 2 barriers),
// then handles window rank t: gather, bilinear 2->4, (1+gmap) scale, write.
// jax half-pixel bilinear 2->4 weights: {1,0},{.75,.25},{.25,.75},{0,1}.
// ---------------------------------------------------------------------------
__global__ void __launch_bounds__(256) k_tail(const float* __restrict__ x,
                                              float* __restrict__ out) {
    int b = blockIdx.x / 3;
    int t = blockIdx.x % 3;
    __shared__ float wv[8][3];
    __shared__ int   wi[8][3];
    __shared__ int   sidx[3];
    __shared__ float s_gmap[16];
    int tid = threadIdx.x;
    int warp = tid >> 5, lane = tid & 31;

    if (tid < 16) s_gmap[tid] = g_gmap[tid];

    float rv[3] = {-FLT_MAX, -FLT_MAX, -FLT_MAX};
    int   ri[3] = {1 << 30, 1 << 30, 1 << 30};
#pragma unroll
    for (int k = 0; k < 4; ++k) {
        int i = tid + k * 256;
        insert3(__ldg(&g_winsum[b * 1024 + i]), i, rv, ri);
    }
#pragma unroll
    for (int o = 16; o > 0; o >>= 1) {
        float ov[3]; int oi[3];
#pragma unroll
        for (int s = 0; s < 3; ++s) {
            ov[s] = __shfl_down_sync(0xffffffffu, rv[s], o);
            oi[s] = __shfl_down_sync(0xffffffffu, ri[s], o);
        }
#pragma unroll
        for (int s = 0; s < 3; ++s) insert3(ov[s], oi[s], rv, ri);
    }
    if (lane == 0) {
#pragma unroll
        for (int s = 0; s < 3; ++s) { wv[warp][s] = rv[s]; wi[warp][s] = ri[s]; }
    }
    __syncthreads();

    if (warp == 0) {
        float fv[3] = {-FLT_MAX, -FLT_MAX, -FLT_MAX};
        int   fi[3] = {1 << 30, 1 << 30, 1 << 30};
        if (lane < 8) {
#pragma unroll
            for (int s = 0; s < 3; ++s) { fv[s] = wv[lane][s]; fi[s] = wi[lane][s]; }
        }
#pragma unroll
        for (int o = 4; o > 0; o >>= 1) {
            float ov[3]; int oi[3];
#pragma unroll
            for (int s = 0; s < 3; ++s) {
                ov[s] = __shfl_down_sync(0xffffffffu, fv[s], o);
                oi[s] = __shfl_down_sync(0xffffffffu, fi[s], o);
            }
#pragma unroll
            for (int s = 0; s < 3; ++s) insert3(ov[s], oi[s], fv, fi);
        }
        if (lane == 0) {
#pragma unroll
            for (int s = 0; s < 3; ++s) sidx[s] = fi[s];
        }
    }
    __syncthreads();

    const float wa[4] = {1.f, 0.75f, 0.25f, 0.f};
    const float wb[4] = {0.f, 0.25f, 0.75f, 1.f};
    int c = tid;

    int widx = sidx[t];
    int wh = widx >> 5, ww = widx & 31;
    const float* p = x + ((size_t)b * 4096 + wh * 128 + ww * 2) * 256 + c;
    float v00 = p[0];          // (i=0,j=0)
    float v01 = p[256];        // (i=0,j=1)
    float v10 = p[64 * 256];   // (i=1,j=0)
    float v11 = p[65 * 256];   // (i=1,j=1)

    float* ob = out + ((size_t)b * 48 + t * 16) * 256 + c;
#pragma unroll
    for (int gh = 0; gh < 4; ++gh) {
        float u0 = wa[gh] * v00 + wb[gh] * v10;  // interp along i (rows)
        float u1 = wa[gh] * v01 + wb[gh] * v11;
#pragma unroll
        for (int gw = 0; gw < 4; ++gw) {
            float val = wa[gw] * u0 + wb[gw] * u1;  // interp along j (cols)
            ob[(gh * 4 + gw) * 256] = val * s_gmap[gh * 4 + gw];
        }
    }
}

// ---------------------------------------------------------------------------
extern "C" void kernel_launch(void* const* d_in, const int* in_sizes, int n_in,
                              void* d_out, int out_size) {
    const float* z   = (const float*)d_in[0];
    const float* x   = (const float*)d_in[1];
    const float* gth = (const float*)d_in[2];
    const float* gsg = (const float*)d_in[3];
    const float* glm = (const float*)d_in[4];
    const float* gps = (const float*)d_in[5];
    const float* ggm = (const float*)d_in[6];
    const float* gwt = (const float*)d_in[7];
    float* out = (float*)d_out;

    int B = in_sizes[0] / (64 * 256);   // z is (B, 64, 256)

    k_main<<<B * 4 + 1 + B * 16, 256>>>(x, z, B, gth, gsg, glm, gps, ggm, gwt);
    k_tail<<<B * 3,              256>>>(x, out);
}